// round 9
// baseline (speedup 1.0000x reference)
#include <cuda_runtime.h>
#include <cuda_bf16.h>

// Problem constants (fixed by the dataset).
#define E_CNT 500000
#define P_CNT 4000000
#define D_DIM 64
#define U_DIM 64

#define SCAN_BLK 1024
#define NSCAN ((E_CNT + SCAN_BLK - 1) / SCAN_BLK)   // 489

// Device scratch (no allocs allowed). Total ~22 MB.
__device__ int g_cnt[E_CNT];        // per-dst edge counts
__device__ int g_off[E_CNT];        // exclusive prefix (global)
__device__ int g_cursor[E_CNT];     // running cursors for reorder
__device__ int g_blocksum[NSCAN];
__device__ int g_srcs[P_CNT];       // src indices sorted by dst

// ---------------------------------------------------------------------------
// 1. Zero the histogram.
// ---------------------------------------------------------------------------
__global__ void k_zero_cnt() {
    int i = blockIdx.x * blockDim.x + threadIdx.x;       // int4 index
    const int n4 = E_CNT / 4;                            // 125000
    if (i < n4) reinterpret_cast<int4*>(g_cnt)[i] = make_int4(0, 0, 0, 0);
}

// ---------------------------------------------------------------------------
// 2. Histogram of destinations.
// ---------------------------------------------------------------------------
__global__ void __launch_bounds__(256) k_hist(const int2* __restrict__ nbr) {
    int p = blockIdx.x * blockDim.x + threadIdx.x;
    if (p < P_CNT) atomicAdd(&g_cnt[__ldg(&nbr[p]).x], 1);
}

// ---------------------------------------------------------------------------
// 3. Block-local exclusive scan (Hillis-Steele, 1024/block) + block sums.
// ---------------------------------------------------------------------------
__global__ void __launch_bounds__(SCAN_BLK) k_scan_block() {
    __shared__ int tmp[SCAN_BLK];
    int t = threadIdx.x;
    int gid = blockIdx.x * SCAN_BLK + t;
    int v = (gid < E_CNT) ? g_cnt[gid] : 0;
    tmp[t] = v;
    __syncthreads();
#pragma unroll
    for (int d = 1; d < SCAN_BLK; d <<= 1) {
        int x = (t >= d) ? tmp[t - d] : 0;
        __syncthreads();
        tmp[t] += x;
        __syncthreads();
    }
    if (gid < E_CNT) g_off[gid] = tmp[t] - v;            // exclusive, block-local
    if (t == SCAN_BLK - 1) g_blocksum[blockIdx.x] = tmp[t];
}

// ---------------------------------------------------------------------------
// 4. Globalize offsets; init cursors. 489-entry blocksum prefix computed
//    inline per block (warp 0 strided partials + warp reduce). Verified
//    correct + cheap (8 us) in round 6; kept.
// ---------------------------------------------------------------------------
__global__ void __launch_bounds__(256) k_scan_add() {
    __shared__ int s_off;
    int sb = blockIdx.x >> 2;          // owning 1024-wide scan block
    if (threadIdx.x < 32) {
        int acc = 0;
        for (int i = threadIdx.x; i < sb; i += 32) acc += __ldg(&g_blocksum[i]);
#pragma unroll
        for (int d = 16; d > 0; d >>= 1) acc += __shfl_xor_sync(~0u, acc, d);
        if (threadIdx.x == 0) s_off = acc;
    }
    __syncthreads();
    int i = blockIdx.x * blockDim.x + threadIdx.x;
    if (i < E_CNT) {
        int o = g_off[i] + s_off;
        g_off[i] = o;
        g_cursor[i] = o;
    }
}

// ---------------------------------------------------------------------------
// 5. Reorder: scatter src ids into dst-sorted order. (Plain stores — the
//    round-6 .cs hints regressed; reverted.)
// ---------------------------------------------------------------------------
__global__ void __launch_bounds__(256) k_reorder(const int2* __restrict__ nbr) {
    int p = blockIdx.x * blockDim.x + threadIdx.x;
    if (p < P_CNT) {
        int2 e = __ldg(&nbr[p]);
        int pos = atomicAdd(&g_cursor[e.x], 1);
        g_srcs[pos] = e.y;
    }
}

// ---------------------------------------------------------------------------
// 6. Fused segmented-sum + GEMM + bias. 64 dst rows per block (8 warps x
//    8 sequential rows each).
//    Phase A: warp w aggregates rows [w*8, w*8+8); lane owns 2 cols
//    (float2), 4-way unrolled gathers. 8 segments/warp shrinks the barrier
//    tail: warp-work spread drops from ~1.7x (1 seg/warp) to ~1.28x.
//    Phase B: Kreg[64] per thread (round-5 proven form, reverting the
//    round-6 k-tiling) now amortized over 16 rows instead of 2.
// ---------------------------------------------------------------------------
__global__ void __launch_bounds__(256, 2) k_fused(
    const float2* __restrict__ F2, const float* __restrict__ Kmat,
    const float* __restrict__ bias, float* __restrict__ out) {
    __shared__ float S[64][64];   // 16 KB

    int warp = threadIdx.x >> 5;
    int lane = threadIdx.x & 31;
    int rowBase = blockIdx.x * 64;

    // ---- Phase A: gather + accumulate, 8 rows per warp ----
#pragma unroll 1
    for (int r = 0; r < 8; r++) {
        int dst = rowBase + warp * 8 + r;
        float ax = 0.f, ay = 0.f;
        if (dst < E_CNT) {
            int s = __ldg(&g_off[dst]);
            int e = (dst == E_CNT - 1) ? P_CNT : __ldg(&g_off[dst + 1]);
            int i = s;
            for (; i + 4 <= e; i += 4) {
                int s0 = __ldg(&g_srcs[i + 0]);
                int s1 = __ldg(&g_srcs[i + 1]);
                int s2 = __ldg(&g_srcs[i + 2]);
                int s3 = __ldg(&g_srcs[i + 3]);
                float2 v0 = __ldg(&F2[(size_t)s0 * 32 + lane]);
                float2 v1 = __ldg(&F2[(size_t)s1 * 32 + lane]);
                float2 v2 = __ldg(&F2[(size_t)s2 * 32 + lane]);
                float2 v3 = __ldg(&F2[(size_t)s3 * 32 + lane]);
                ax += (v0.x + v1.x) + (v2.x + v3.x);
                ay += (v0.y + v1.y) + (v2.y + v3.y);
            }
            for (; i < e; i++) {
                int s0 = __ldg(&g_srcs[i]);
                float2 v = __ldg(&F2[(size_t)s0 * 32 + lane]);
                ax += v.x;
                ay += v.y;
            }
        }
        reinterpret_cast<float2*>(S[warp * 8 + r])[lane] = make_float2(ax, ay);
    }
    __syncthreads();

    // ---- Phase B: out[row] = S[row] . K[:,u] + b ----
    // Group g (64 threads) handles rows [g*16, g*16+16) in 4 chunks of 4.
    int u = threadIdx.x & 63;
    int g = threadIdx.x >> 6;
    float b = __ldg(&bias[u]);

    float Kreg[64];
#pragma unroll
    for (int k = 0; k < 64; k++) Kreg[k] = __ldg(&Kmat[k * U_DIM + u]);

#pragma unroll
    for (int c = 0; c < 4; c++) {
        int r0 = g * 16 + c * 4;
        float acc0 = b, acc1 = b, acc2 = b, acc3 = b;
#pragma unroll
        for (int k4 = 0; k4 < 16; k4++) {
            float4 x0 = reinterpret_cast<const float4*>(S[r0 + 0])[k4];
            float4 x1 = reinterpret_cast<const float4*>(S[r0 + 1])[k4];
            float4 x2 = reinterpret_cast<const float4*>(S[r0 + 2])[k4];
            float4 x3 = reinterpret_cast<const float4*>(S[r0 + 3])[k4];
            float k0 = Kreg[4 * k4 + 0], k1 = Kreg[4 * k4 + 1];
            float k2 = Kreg[4 * k4 + 2], k3 = Kreg[4 * k4 + 3];
            acc0 = fmaf(x0.x, k0, fmaf(x0.y, k1, fmaf(x0.z, k2, fmaf(x0.w, k3, acc0))));
            acc1 = fmaf(x1.x, k0, fmaf(x1.y, k1, fmaf(x1.z, k2, fmaf(x1.w, k3, acc1))));
            acc2 = fmaf(x2.x, k0, fmaf(x2.y, k1, fmaf(x2.z, k2, fmaf(x2.w, k3, acc2))));
            acc3 = fmaf(x3.x, k0, fmaf(x3.y, k1, fmaf(x3.z, k2, fmaf(x3.w, k3, acc3))));
        }
        size_t gr = (size_t)rowBase + r0;
        if (gr + 0 < E_CNT) out[(gr + 0) * U_DIM + u] = acc0;
        if (gr + 1 < E_CNT) out[(gr + 1) * U_DIM + u] = acc1;
        if (gr + 2 < E_CNT) out[(gr + 2) * U_DIM + u] = acc2;
        if (gr + 3 < E_CNT) out[(gr + 3) * U_DIM + u] = acc3;
    }
}

// ---------------------------------------------------------------------------
// Launch pipeline (graph-capturable: kernels only, no sync, no allocs).
// ---------------------------------------------------------------------------
extern "C" void kernel_launch(void* const* d_in, const int* in_sizes, int n_in,
                              void* d_out, int out_size) {
    const float* feat = (const float*)d_in[0];   // [E, 64] fp32
    const int*   nbr  = (const int*)d_in[1];     // [P, 2]  int32
    const float* Kmat = (const float*)d_in[2];   // [64, 64] fp32
    const float* bias = (const float*)d_in[3];   // [64] fp32
    float* out = (float*)d_out;                  // [E, 64] fp32

    k_zero_cnt<<<(E_CNT / 4 + 255) / 256, 256>>>();
    k_hist<<<P_CNT / 256, 256>>>((const int2*)nbr);
    k_scan_block<<<NSCAN, SCAN_BLK>>>();
    k_scan_add<<<(E_CNT + 255) / 256, 256>>>();
    k_reorder<<<P_CNT / 256, 256>>>((const int2*)nbr);
    k_fused<<<(E_CNT + 63) / 64, 256>>>((const float2*)feat, Kmat, bias, out);
}

// round 12
// speedup vs baseline: 1.1944x; 1.1944x over previous
#include <cuda_runtime.h>
#include <cuda_bf16.h>

// Problem constants (fixed by the dataset).
#define E_CNT 500000
#define P_CNT 4000000
#define D_DIM 64
#define U_DIM 64

#define SCAN_BLK 1024
#define NSCAN ((E_CNT + SCAN_BLK - 1) / SCAN_BLK)   // 489

// Device scratch (no allocs allowed). Total ~22 MB.
__device__ int g_cnt[E_CNT];        // per-dst edge counts
__device__ int g_off[E_CNT];        // exclusive prefix (global)
__device__ int g_cursor[E_CNT];     // running cursors for reorder
__device__ int g_blocksum[NSCAN];
__device__ int g_srcs[P_CNT];       // src indices sorted by dst

// ---------------------------------------------------------------------------
// 1. Zero the histogram.
// ---------------------------------------------------------------------------
__global__ void k_zero_cnt() {
    int i = blockIdx.x * blockDim.x + threadIdx.x;       // int4 index
    const int n4 = E_CNT / 4;                            // 125000
    if (i < n4) reinterpret_cast<int4*>(g_cnt)[i] = make_int4(0, 0, 0, 0);
}

// ---------------------------------------------------------------------------
// 2. Histogram of destinations.
// ---------------------------------------------------------------------------
__global__ void __launch_bounds__(256) k_hist(const int2* __restrict__ nbr) {
    int p = blockIdx.x * blockDim.x + threadIdx.x;
    if (p < P_CNT) atomicAdd(&g_cnt[__ldg(&nbr[p]).x], 1);
}

// ---------------------------------------------------------------------------
// 3. Block-local exclusive scan (Hillis-Steele, 1024/block) + block sums.
// ---------------------------------------------------------------------------
__global__ void __launch_bounds__(SCAN_BLK) k_scan_block() {
    __shared__ int tmp[SCAN_BLK];
    int t = threadIdx.x;
    int gid = blockIdx.x * SCAN_BLK + t;
    int v = (gid < E_CNT) ? g_cnt[gid] : 0;
    tmp[t] = v;
    __syncthreads();
#pragma unroll
    for (int d = 1; d < SCAN_BLK; d <<= 1) {
        int x = (t >= d) ? tmp[t - d] : 0;
        __syncthreads();
        tmp[t] += x;
        __syncthreads();
    }
    if (gid < E_CNT) g_off[gid] = tmp[t] - v;            // exclusive, block-local
    if (t == SCAN_BLK - 1) g_blocksum[blockIdx.x] = tmp[t];
}

// ---------------------------------------------------------------------------
// 4. Globalize offsets; init cursors (inline blocksum prefix — verified
//    neutral/cheap in rounds 6-9; kept).
// ---------------------------------------------------------------------------
__global__ void __launch_bounds__(256) k_scan_add() {
    __shared__ int s_off;
    int sb = blockIdx.x >> 2;          // owning 1024-wide scan block
    if (threadIdx.x < 32) {
        int acc = 0;
        for (int i = threadIdx.x; i < sb; i += 32) acc += __ldg(&g_blocksum[i]);
#pragma unroll
        for (int d = 16; d > 0; d >>= 1) acc += __shfl_xor_sync(~0u, acc, d);
        if (threadIdx.x == 0) s_off = acc;
    }
    __syncthreads();
    int i = blockIdx.x * blockDim.x + threadIdx.x;
    if (i < E_CNT) {
        int o = g_off[i] + s_off;
        g_off[i] = o;
        g_cursor[i] = o;
    }
}

// ---------------------------------------------------------------------------
// 5. Reorder: scatter src ids into dst-sorted order (plain stores).
// ---------------------------------------------------------------------------
__global__ void __launch_bounds__(256) k_reorder(const int2* __restrict__ nbr) {
    int p = blockIdx.x * blockDim.x + threadIdx.x;
    if (p < P_CNT) {
        int2 e = __ldg(&nbr[p]);
        int pos = atomicAdd(&g_cursor[e.x], 1);
        g_srcs[pos] = e.y;
    }
}

// ---------------------------------------------------------------------------
// 6. Fused segmented-sum + GEMM + bias — round-5 proven structure
//    (8 warps/block, ONE segment per warp, 8 rows/block), with two changes:
//    (a) K lives in SMEM (16 KB, cooperative load, conflict-free scalar LDS
//        in Phase B) instead of 64 registers/thread -> regs ~40 ->
//        __launch_bounds__(256,5): 5 resident blocks/SM instead of 2.
//        Cross-block warps now hide the gather latency chain + barrier tail.
//    (b) Gather unrolled x8 (MLP 8; 2 KB in flight per warp).
// ---------------------------------------------------------------------------
__global__ void __launch_bounds__(256, 5) k_fused(
    const float2* __restrict__ F2, const float* __restrict__ Kmat,
    const float* __restrict__ bias, float* __restrict__ out) {
    __shared__ float Ks[64 * 64];   // 16 KB: K row-major [k][u]
    __shared__ float S[8][64];      // 2 KB: aggregated rows

    // Cooperative K load: 1024 float4 by 256 threads, coalesced.
    {
        const float4* K4 = reinterpret_cast<const float4*>(Kmat);
        float4* Ks4 = reinterpret_cast<float4*>(Ks);
#pragma unroll
        for (int i = 0; i < 4; i++)
            Ks4[threadIdx.x + 256 * i] = __ldg(&K4[threadIdx.x + 256 * i]);
    }

    int warp = threadIdx.x >> 5;
    int lane = threadIdx.x & 31;
    int dst = blockIdx.x * 8 + warp;

    // ---- Phase A: gather + accumulate (1 segment per warp) ----
    int s = __ldg(&g_off[dst]);
    int e = (dst == E_CNT - 1) ? P_CNT : __ldg(&g_off[dst + 1]);

    float ax = 0.f, ay = 0.f;
    int i = s;
    for (; i + 8 <= e; i += 8) {
        int s0 = __ldg(&g_srcs[i + 0]);
        int s1 = __ldg(&g_srcs[i + 1]);
        int s2 = __ldg(&g_srcs[i + 2]);
        int s3 = __ldg(&g_srcs[i + 3]);
        int s4 = __ldg(&g_srcs[i + 4]);
        int s5 = __ldg(&g_srcs[i + 5]);
        int s6 = __ldg(&g_srcs[i + 6]);
        int s7 = __ldg(&g_srcs[i + 7]);
        float2 v0 = __ldg(&F2[(size_t)s0 * 32 + lane]);
        float2 v1 = __ldg(&F2[(size_t)s1 * 32 + lane]);
        float2 v2 = __ldg(&F2[(size_t)s2 * 32 + lane]);
        float2 v3 = __ldg(&F2[(size_t)s3 * 32 + lane]);
        float2 v4 = __ldg(&F2[(size_t)s4 * 32 + lane]);
        float2 v5 = __ldg(&F2[(size_t)s5 * 32 + lane]);
        float2 v6 = __ldg(&F2[(size_t)s6 * 32 + lane]);
        float2 v7 = __ldg(&F2[(size_t)s7 * 32 + lane]);
        ax += ((v0.x + v1.x) + (v2.x + v3.x)) + ((v4.x + v5.x) + (v6.x + v7.x));
        ay += ((v0.y + v1.y) + (v2.y + v3.y)) + ((v4.y + v5.y) + (v6.y + v7.y));
    }
    for (; i + 4 <= e; i += 4) {
        int s0 = __ldg(&g_srcs[i + 0]);
        int s1 = __ldg(&g_srcs[i + 1]);
        int s2 = __ldg(&g_srcs[i + 2]);
        int s3 = __ldg(&g_srcs[i + 3]);
        float2 v0 = __ldg(&F2[(size_t)s0 * 32 + lane]);
        float2 v1 = __ldg(&F2[(size_t)s1 * 32 + lane]);
        float2 v2 = __ldg(&F2[(size_t)s2 * 32 + lane]);
        float2 v3 = __ldg(&F2[(size_t)s3 * 32 + lane]);
        ax += (v0.x + v1.x) + (v2.x + v3.x);
        ay += (v0.y + v1.y) + (v2.y + v3.y);
    }
    for (; i < e; i++) {
        int s0 = __ldg(&g_srcs[i]);
        float2 v = __ldg(&F2[(size_t)s0 * 32 + lane]);
        ax += v.x;
        ay += v.y;
    }
    reinterpret_cast<float2*>(S[warp])[lane] = make_float2(ax, ay);

    float b = __ldg(&bias[threadIdx.x & 63]);
    __syncthreads();   // covers both Ks and S

    // ---- Phase B: out[row] = S[row] . K[:,u] + b ----
    // Group g (64 threads) handles rows 2g, 2g+1. K read from smem:
    // threads u=0..63 read consecutive words per k -> conflict-free LDS.
    int u = threadIdx.x & 63;
    int g = threadIdx.x >> 6;

    const float4* R0 = reinterpret_cast<const float4*>(S[2 * g + 0]);
    const float4* R1 = reinterpret_cast<const float4*>(S[2 * g + 1]);
    float acc0 = b, acc1 = b;
#pragma unroll
    for (int k4 = 0; k4 < 16; k4++) {
        float4 x = R0[k4];
        float4 y = R1[k4];
        float k0 = Ks[(4 * k4 + 0) * 64 + u];
        float k1 = Ks[(4 * k4 + 1) * 64 + u];
        float k2 = Ks[(4 * k4 + 2) * 64 + u];
        float k3 = Ks[(4 * k4 + 3) * 64 + u];
        acc0 = fmaf(x.x, k0, fmaf(x.y, k1, fmaf(x.z, k2, fmaf(x.w, k3, acc0))));
        acc1 = fmaf(y.x, k0, fmaf(y.y, k1, fmaf(y.z, k2, fmaf(y.w, k3, acc1))));
    }

    size_t rowA = ((size_t)blockIdx.x * 8 + 2 * g) * U_DIM;
    out[rowA + u]         = acc0;
    out[rowA + U_DIM + u] = acc1;
}

// ---------------------------------------------------------------------------
// Launch pipeline (graph-capturable: kernels only, no sync, no allocs).
// ---------------------------------------------------------------------------
extern "C" void kernel_launch(void* const* d_in, const int* in_sizes, int n_in,
                              void* d_out, int out_size) {
    const float* feat = (const float*)d_in[0];   // [E, 64] fp32
    const int*   nbr  = (const int*)d_in[1];     // [P, 2]  int32
    const float* Kmat = (const float*)d_in[2];   // [64, 64] fp32
    const float* bias = (const float*)d_in[3];   // [64] fp32
    float* out = (float*)d_out;                  // [E, 64] fp32

    k_zero_cnt<<<(E_CNT / 4 + 255) / 256, 256>>>();
    k_hist<<<P_CNT / 256, 256>>>((const int2*)nbr);
    k_scan_block<<<NSCAN, SCAN_BLK>>>();
    k_scan_add<<<(E_CNT + 255) / 256, 256>>>();
    k_reorder<<<P_CNT / 256, 256>>>((const int2*)nbr);
    k_fused<<<E_CNT / 8, 256>>>((const float2*)feat, Kmat, bias, out);
}

// round 13
// speedup vs baseline: 1.3965x; 1.1692x over previous
#include <cuda_runtime.h>
#include <cuda_fp16.h>
#include <cuda_bf16.h>

// Problem constants (fixed by the dataset).
#define E_CNT 500000
#define P_CNT 4000000
#define D_DIM 64
#define U_DIM 64

#define SCAN_BLK 1024
#define NSCAN ((E_CNT + SCAN_BLK - 1) / SCAN_BLK)   // 489

// Device scratch (no allocs allowed). ~86 MB total.
__device__ int g_cnt[E_CNT];          // per-dst edge counts
__device__ int g_off[E_CNT];          // exclusive prefix (global)
__device__ int g_cursor[E_CNT];       // running cursors for reorder
__device__ int g_blocksum[NSCAN];
__device__ int g_srcs[P_CNT];         // src indices sorted by dst
__device__ __half2 g_fh[(size_t)E_CNT * 32];  // fp16 feature table, 64 MB

// ---------------------------------------------------------------------------
// 1. Zero the histogram.
// ---------------------------------------------------------------------------
__global__ void k_zero_cnt() {
    int i = blockIdx.x * blockDim.x + threadIdx.x;       // int4 index
    const int n4 = E_CNT / 4;                            // 125000
    if (i < n4) reinterpret_cast<int4*>(g_cnt)[i] = make_int4(0, 0, 0, 0);
}

// ---------------------------------------------------------------------------
// 2. Histogram of destinations.
// ---------------------------------------------------------------------------
__global__ void __launch_bounds__(256) k_hist(const int2* __restrict__ nbr) {
    int p = blockIdx.x * blockDim.x + threadIdx.x;
    if (p < P_CNT) atomicAdd(&g_cnt[__ldg(&nbr[p]).x], 1);
}

// ---------------------------------------------------------------------------
// 3. Block-local exclusive scan (Hillis-Steele, 1024/block) + block sums.
// ---------------------------------------------------------------------------
__global__ void __launch_bounds__(SCAN_BLK) k_scan_block() {
    __shared__ int tmp[SCAN_BLK];
    int t = threadIdx.x;
    int gid = blockIdx.x * SCAN_BLK + t;
    int v = (gid < E_CNT) ? g_cnt[gid] : 0;
    tmp[t] = v;
    __syncthreads();
#pragma unroll
    for (int d = 1; d < SCAN_BLK; d <<= 1) {
        int x = (t >= d) ? tmp[t - d] : 0;
        __syncthreads();
        tmp[t] += x;
        __syncthreads();
    }
    if (gid < E_CNT) g_off[gid] = tmp[t] - v;            // exclusive, block-local
    if (t == SCAN_BLK - 1) g_blocksum[blockIdx.x] = tmp[t];
}

// ---------------------------------------------------------------------------
// 4. Globalize offsets; init cursors (inline blocksum prefix).
// ---------------------------------------------------------------------------
__global__ void __launch_bounds__(256) k_scan_add() {
    __shared__ int s_off;
    int sb = blockIdx.x >> 2;          // owning 1024-wide scan block
    if (threadIdx.x < 32) {
        int acc = 0;
        for (int i = threadIdx.x; i < sb; i += 32) acc += __ldg(&g_blocksum[i]);
#pragma unroll
        for (int d = 16; d > 0; d >>= 1) acc += __shfl_xor_sync(~0u, acc, d);
        if (threadIdx.x == 0) s_off = acc;
    }
    __syncthreads();
    int i = blockIdx.x * blockDim.x + threadIdx.x;
    if (i < E_CNT) {
        int o = g_off[i] + s_off;
        g_off[i] = o;
        g_cursor[i] = o;
    }
}

// ---------------------------------------------------------------------------
// 5. Reorder: scatter src ids into dst-sorted order (plain stores).
// ---------------------------------------------------------------------------
__global__ void __launch_bounds__(256) k_reorder(const int2* __restrict__ nbr) {
    int p = blockIdx.x * blockDim.x + threadIdx.x;
    if (p < P_CNT) {
        int2 e = __ldg(&nbr[p]);
        int pos = atomicAdd(&g_cursor[e.x], 1);
        g_srcs[pos] = e.y;
    }
}

// ---------------------------------------------------------------------------
// 6. Convert feature table fp32 -> fp16 (streaming; 128 MB read, 64 MB
//    write). The 64 MB fp16 table fits L2 together with g_srcs, so the
//    gather phase becomes L2-resident instead of DRAM-miss-bound.
// ---------------------------------------------------------------------------
__global__ void __launch_bounds__(256) k_convert(const float4* __restrict__ f4) {
    int i = blockIdx.x * blockDim.x + threadIdx.x;       // uint4 output index
    const int n = (int)((size_t)E_CNT * 32 / 4);         // 4,000,000
    if (i < n) {
        float4 a = __ldg(&f4[2 * i + 0]);
        float4 b = __ldg(&f4[2 * i + 1]);
        __half2 h0 = __floats2half2_rn(a.x, a.y);
        __half2 h1 = __floats2half2_rn(a.z, a.w);
        __half2 h2 = __floats2half2_rn(b.x, b.y);
        __half2 h3 = __floats2half2_rn(b.z, b.w);
        uint4 w;
        w.x = *reinterpret_cast<unsigned*>(&h0);
        w.y = *reinterpret_cast<unsigned*>(&h1);
        w.z = *reinterpret_cast<unsigned*>(&h2);
        w.w = *reinterpret_cast<unsigned*>(&h3);
        reinterpret_cast<uint4*>(g_fh)[i] = w;
    }
}

// ---------------------------------------------------------------------------
// 7. Fused segmented-sum + GEMM + bias — EXACT round-5 structure (best
//    measured: 385us): 8 warps/block, one segment per warp, lane owns 2
//    cols, x4 unrolled gather, Kreg[64] in registers, 4 groups x 2 rows in
//    Phase B. Single change: gathers read the fp16 table (4 B/lane, fp32
//    accumulation) -> half the gather bytes and an L2-resident table.
// ---------------------------------------------------------------------------
__global__ void __launch_bounds__(256) k_fused(
    const float* __restrict__ Kmat, const float* __restrict__ bias,
    float* __restrict__ out) {
    __shared__ float S[8][64];

    int warp = threadIdx.x >> 5;
    int lane = threadIdx.x & 31;
    int dst = blockIdx.x * 8 + warp;

    // ---- Phase A: gather + accumulate ----
    int s = __ldg(&g_off[dst]);
    int e = (dst == E_CNT - 1) ? P_CNT : __ldg(&g_off[dst + 1]);

    float ax = 0.f, ay = 0.f;
    int i = s;
    for (; i + 4 <= e; i += 4) {
        int s0 = __ldg(&g_srcs[i + 0]);
        int s1 = __ldg(&g_srcs[i + 1]);
        int s2 = __ldg(&g_srcs[i + 2]);
        int s3 = __ldg(&g_srcs[i + 3]);
        __half2 h0 = g_fh[(size_t)s0 * 32 + lane];
        __half2 h1 = g_fh[(size_t)s1 * 32 + lane];
        __half2 h2 = g_fh[(size_t)s2 * 32 + lane];
        __half2 h3 = g_fh[(size_t)s3 * 32 + lane];
        float2 v0 = __half22float2(h0);
        float2 v1 = __half22float2(h1);
        float2 v2 = __half22float2(h2);
        float2 v3 = __half22float2(h3);
        ax += (v0.x + v1.x) + (v2.x + v3.x);
        ay += (v0.y + v1.y) + (v2.y + v3.y);
    }
    for (; i < e; i++) {
        int s0 = __ldg(&g_srcs[i]);
        float2 v = __half22float2(g_fh[(size_t)s0 * 32 + lane]);
        ax += v.x;
        ay += v.y;
    }
    reinterpret_cast<float2*>(S[warp])[lane] = make_float2(ax, ay);

    // ---- Load K column (independent of smem; overlaps with sync) ----
    int u = threadIdx.x & 63;
    int g = threadIdx.x >> 6;  // 0..3 -> rows 2g, 2g+1
    float Kreg[64];
#pragma unroll
    for (int k = 0; k < 64; k++) Kreg[k] = __ldg(&Kmat[k * U_DIM + u]);
    float b = __ldg(&bias[u]);

    __syncthreads();

    // ---- Phase B: out[row] = S[row] . K[:,u] + b ----
    const float4* R0 = reinterpret_cast<const float4*>(S[2 * g + 0]);
    const float4* R1 = reinterpret_cast<const float4*>(S[2 * g + 1]);
    float acc0 = 0.f, acc1 = 0.f;
#pragma unroll
    for (int k4 = 0; k4 < 16; k4++) {
        float4 x = R0[k4];
        float4 y = R1[k4];
        acc0 = fmaf(x.x, Kreg[4 * k4 + 0],
               fmaf(x.y, Kreg[4 * k4 + 1],
               fmaf(x.z, Kreg[4 * k4 + 2],
               fmaf(x.w, Kreg[4 * k4 + 3], acc0))));
        acc1 = fmaf(y.x, Kreg[4 * k4 + 0],
               fmaf(y.y, Kreg[4 * k4 + 1],
               fmaf(y.z, Kreg[4 * k4 + 2],
               fmaf(y.w, Kreg[4 * k4 + 3], acc1))));
    }

    size_t rowA = ((size_t)blockIdx.x * 8 + 2 * g) * U_DIM;
    out[rowA + u]         = acc0 + b;
    out[rowA + U_DIM + u] = acc1 + b;
}

// ---------------------------------------------------------------------------
// Launch pipeline (graph-capturable: kernels only, no sync, no allocs).
// k_convert placed right before k_fused so the fp16 table is L2-warm.
// ---------------------------------------------------------------------------
extern "C" void kernel_launch(void* const* d_in, const int* in_sizes, int n_in,
                              void* d_out, int out_size) {
    const float* feat = (const float*)d_in[0];   // [E, 64] fp32
    const int*   nbr  = (const int*)d_in[1];     // [P, 2]  int32
    const float* Kmat = (const float*)d_in[2];   // [64, 64] fp32
    const float* bias = (const float*)d_in[3];   // [64] fp32
    float* out = (float*)d_out;                  // [E, 64] fp32

    k_zero_cnt<<<(E_CNT / 4 + 255) / 256, 256>>>();
    k_hist<<<P_CNT / 256, 256>>>((const int2*)nbr);
    k_scan_block<<<NSCAN, SCAN_BLK>>>();
    k_scan_add<<<(E_CNT + 255) / 256, 256>>>();
    k_reorder<<<P_CNT / 256, 256>>>((const int2*)nbr);
    k_convert<<<(E_CNT * 32 / 4 + 255) / 256, 256>>>((const float4*)feat);
    k_fused<<<E_CNT / 8, 256>>>(Kmat, bias, out);
}